// round 14
// baseline (speedup 1.0000x reference)
#include <cuda_runtime.h>
#include <math.h>

// Packed accumulator: bits [44:) = block counter, bits [0:44) = biased
// fixed-point (2^20) cosine sum. Last block writes out + resets -> replay-safe.
__device__ unsigned long long g_acc = 0ULL;

#define FIX_ONE   (1048576.0f)            // 2^20
#define BIAS      (1LL << 24)
#define CNT_SHIFT 44
#define SUM_MASK  ((1ULL << CNT_SHIFT) - 1ULL)

// --- Single fused kernel: warp-per-sample; label -> 4 emb loads -> 4 proto
//     loads fully batched (MLP=8). minBlocks=4 relaxes the reg budget so
//     ptxas KEEPS the batch (R13 at default bounds collapsed to 32 regs). ---
__global__ __launch_bounds__(256, 4) void cos_main(
    const float* __restrict__ emb,
    const void*  __restrict__ labels_raw,
    const float* __restrict__ protos,
    float* __restrict__ out,
    int B, int D, int C)
{
    const int wib  = threadIdx.x >> 5;
    const int lane = threadIdx.x & 31;
    const int warp = blockIdx.x * 8 + wib;

    // Per-warp label dtype detection (32B L2-hot broadcast; P(miss) ~ 1e-16).
    const long long* l64 = (const long long*)labels_raw;
    bool is64;
    {
        int nq = B >= 8 ? 4 : (B >= 2 ? B / 2 : 0);
        bool ok = (nq > 0);
        for (int i = 0; i < nq; i++) {
            unsigned long long v = (unsigned long long)l64[i];
            ok &= (v < (unsigned long long)C);
        }
        is64 = ok;
    }

    float dep = 0.f, dee = 0.f, dpp = 0.f;

    if (warp < B) {
        // 1. Label first (latency covered by the independent emb loads).
        long long lab;
        if (is64) lab = l64[warp];
        else      lab = (long long)((const int*)labels_raw)[warp];
        if (lab < 0) lab = 0;
        if (lab >= (long long)C) lab = C - 1;

        if (D == 512) {
            const float4* e = reinterpret_cast<const float4*>(emb + (size_t)warp * 512);
            const float4* p = reinterpret_cast<const float4*>(protos + (size_t)lab * 512);

            // 2. Four independent embedding loads.
            float4 ev[4];
            #pragma unroll
            for (int k = 0; k < 4; k++) ev[k] = e[lane + 32 * k];

            // 3. Four prototype loads (label now resolved).
            float4 pv[4];
            #pragma unroll
            for (int k = 0; k < 4; k++) pv[k] = p[lane + 32 * k];

            // 4. Math only after all 8 loads are issued.
            #pragma unroll
            for (int k = 0; k < 4; k++) {
                dep = fmaf(ev[k].x, pv[k].x, fmaf(ev[k].y, pv[k].y,
                      fmaf(ev[k].z, pv[k].z, fmaf(ev[k].w, pv[k].w, dep))));
                dee = fmaf(ev[k].x, ev[k].x, fmaf(ev[k].y, ev[k].y,
                      fmaf(ev[k].z, ev[k].z, fmaf(ev[k].w, ev[k].w, dee))));
                dpp = fmaf(pv[k].x, pv[k].x, fmaf(pv[k].y, pv[k].y,
                      fmaf(pv[k].z, pv[k].z, fmaf(pv[k].w, pv[k].w, dpp))));
            }
        } else {
            const float* e = emb + (size_t)warp * D;
            const float* p = protos + (size_t)lab * D;
            for (int i = lane; i < D; i += 32) {
                float evs = e[i], pvs = p[i];
                dep = fmaf(evs, pvs, dep);
                dee = fmaf(evs, evs, dee);
                dpp = fmaf(pvs, pvs, dpp);
            }
        }
    }

    #pragma unroll
    for (int off = 16; off > 0; off >>= 1) {
        dep += __shfl_xor_sync(0xFFFFFFFFu, dep, off);
        dee += __shfl_xor_sync(0xFFFFFFFFu, dee, off);
        dpp += __shfl_xor_sync(0xFFFFFFFFu, dpp, off);
    }

    __shared__ float s_cos[8];
    if (lane == 0) {
        float cosv = 0.f;
        if (warp < B) {
            float en = fmaxf(sqrtf(dee), 1e-8f);
            float pn = fmaxf(sqrtf(dpp), 1e-8f);
            cosv = dep / (en * pn);
        }
        s_cos[wib] = cosv;
    }
    __syncthreads();

    if (threadIdx.x == 0) {
        float acc = 0.f;
        #pragma unroll
        for (int w = 0; w < 8; w++) acc += s_cos[w];

        // |acc| <= 8 -> biased fixed-point always positive, no carry into cnt.
        long long fixed = __float2ll_rn(acc * FIX_ONE) + BIAS;
        unsigned long long add = (1ULL << CNT_SHIFT) | (unsigned long long)fixed;
        unsigned long long old = atomicAdd(&g_acc, add);

        if ((unsigned)(old >> CNT_SHIFT) == (unsigned)(gridDim.x - 1)) {
            unsigned long long total = old + add;
            long long fixsum = (long long)(total & SUM_MASK)
                             - (long long)gridDim.x * BIAS;
            double sum = (double)fixsum / (double)FIX_ONE;
            out[0] = 1.0f - (float)(sum / (double)B);
            atomicExch(&g_acc, 0ULL);          // reset for next graph replay
        }
    }
}

extern "C" void kernel_launch(void* const* d_in, const int* in_sizes, int n_in,
                              void* d_out, int out_size)
{
    // metadata order: embeddings [B*D] f32, labels [B], prototypes [C*D] f32
    const float* emb    = (const float*)d_in[0];
    const void*  labels = d_in[1];
    const float* protos = (const float*)d_in[2];
    float*       out    = (float*)d_out;

    const int B = in_sizes[1];
    const int D = in_sizes[0] / B;
    const int C = in_sizes[2] / D;

    int blocks = (B + 7) / 8;                  // 8 warps (samples) per block

    cos_main<<<blocks, 256>>>(emb, labels, protos, out, B, D, C);
}

// round 17
// speedup vs baseline: 1.2193x; 1.2193x over previous
#include <cuda_runtime.h>
#include <math.h>

// Packed accumulator: bits [44:) = block counter, bits [0:44) = biased
// fixed-point (2^20) cosine sum. Last block writes out + resets -> replay-safe.
__device__ unsigned long long g_acc = 0ULL;

#define FIX_ONE   (1048576.0f)            // 2^20
#define BIAS      (1LL << 24)
#define CNT_SHIFT 44
#define SUM_MASK  ((1ULL << CNT_SHIFT) - 1ULL)

// Evict-first float4 load (embeddings are read exactly once).
__device__ __forceinline__ float4 ldcs_f4(const float4* p) {
    return __ldcs(p);
}

// --- Single fused kernel (R13 body): warp-per-sample, default launch bounds
//     (regs=32, occ ~87%). ONLY change: __ldcs on embedding loads so the
//     128 MiB one-shot stream doesn't evict the L2-resident prototypes. -----
__global__ __launch_bounds__(256) void cos_main(
    const float* __restrict__ emb,
    const void*  __restrict__ labels_raw,
    const float* __restrict__ protos,
    float* __restrict__ out,
    int B, int D, int C)
{
    const int wib  = threadIdx.x >> 5;
    const int lane = threadIdx.x & 31;
    const int warp = blockIdx.x * 8 + wib;

    // Per-warp label dtype detection (32B L2-hot broadcast; P(miss) ~ 1e-16).
    const long long* l64 = (const long long*)labels_raw;
    bool is64;
    {
        int nq = B >= 8 ? 4 : (B >= 2 ? B / 2 : 0);
        bool ok = (nq > 0);
        for (int i = 0; i < nq; i++) {
            unsigned long long v = (unsigned long long)l64[i];
            ok &= (v < (unsigned long long)C);
        }
        is64 = ok;
    }

    float dep = 0.f, dee = 0.f, dpp = 0.f;

    if (warp < B) {
        long long lab;
        if (is64) lab = l64[warp];
        else      lab = (long long)((const int*)labels_raw)[warp];
        if (lab < 0) lab = 0;
        if (lab >= (long long)C) lab = C - 1;

        if (D == 512) {
            const float4* e = reinterpret_cast<const float4*>(emb + (size_t)warp * 512);
            const float4* p = reinterpret_cast<const float4*>(protos + (size_t)lab * 512);

            float4 ev[4];
            #pragma unroll
            for (int k = 0; k < 4; k++) ev[k] = ldcs_f4(&e[lane + 32 * k]);

            float4 pv[4];
            #pragma unroll
            for (int k = 0; k < 4; k++) pv[k] = p[lane + 32 * k];

            #pragma unroll
            for (int k = 0; k < 4; k++) {
                dep = fmaf(ev[k].x, pv[k].x, fmaf(ev[k].y, pv[k].y,
                      fmaf(ev[k].z, pv[k].z, fmaf(ev[k].w, pv[k].w, dep))));
                dee = fmaf(ev[k].x, ev[k].x, fmaf(ev[k].y, ev[k].y,
                      fmaf(ev[k].z, ev[k].z, fmaf(ev[k].w, ev[k].w, dee))));
                dpp = fmaf(pv[k].x, pv[k].x, fmaf(pv[k].y, pv[k].y,
                      fmaf(pv[k].z, pv[k].z, fmaf(pv[k].w, pv[k].w, dpp))));
            }
        } else {
            const float* e = emb + (size_t)warp * D;
            const float* p = protos + (size_t)lab * D;
            for (int i = lane; i < D; i += 32) {
                float evs = __ldcs(&e[i]);
                float pvs = p[i];
                dep = fmaf(evs, pvs, dep);
                dee = fmaf(evs, evs, dee);
                dpp = fmaf(pvs, pvs, dpp);
            }
        }
    }

    #pragma unroll
    for (int off = 16; off > 0; off >>= 1) {
        dep += __shfl_xor_sync(0xFFFFFFFFu, dep, off);
        dee += __shfl_xor_sync(0xFFFFFFFFu, dee, off);
        dpp += __shfl_xor_sync(0xFFFFFFFFu, dpp, off);
    }

    __shared__ float s_cos[8];
    if (lane == 0) {
        float cosv = 0.f;
        if (warp < B) {
            float en = fmaxf(sqrtf(dee), 1e-8f);
            float pn = fmaxf(sqrtf(dpp), 1e-8f);
            cosv = dep / (en * pn);
        }
        s_cos[wib] = cosv;
    }
    __syncthreads();

    if (threadIdx.x == 0) {
        float acc = 0.f;
        #pragma unroll
        for (int w = 0; w < 8; w++) acc += s_cos[w];

        // |acc| <= 8 -> biased fixed-point always positive, no carry into cnt.
        long long fixed = __float2ll_rn(acc * FIX_ONE) + BIAS;
        unsigned long long add = (1ULL << CNT_SHIFT) | (unsigned long long)fixed;
        unsigned long long old = atomicAdd(&g_acc, add);

        if ((unsigned)(old >> CNT_SHIFT) == (unsigned)(gridDim.x - 1)) {
            unsigned long long total = old + add;
            long long fixsum = (long long)(total & SUM_MASK)
                             - (long long)gridDim.x * BIAS;
            double sum = (double)fixsum / (double)FIX_ONE;
            out[0] = 1.0f - (float)(sum / (double)B);
            atomicExch(&g_acc, 0ULL);          // reset for next graph replay
        }
    }
}

extern "C" void kernel_launch(void* const* d_in, const int* in_sizes, int n_in,
                              void* d_out, int out_size)
{
    // metadata order: embeddings [B*D] f32, labels [B], prototypes [C*D] f32
    const float* emb    = (const float*)d_in[0];
    const void*  labels = d_in[1];
    const float* protos = (const float*)d_in[2];
    float*       out    = (float*)d_out;

    const int B = in_sizes[1];
    const int D = in_sizes[0] / B;
    const int C = in_sizes[2] / D;

    int blocks = (B + 7) / 8;                  // 8 warps (samples) per block

    cos_main<<<blocks, 256>>>(emb, labels, protos, out, B, D, C);
}